// round 4
// baseline (speedup 1.0000x reference)
#include <cuda_runtime.h>
#include <math.h>
#include <stdint.h>

#define L 512
#define B 32
#define D 256
#define H 256
#define G 768           // 3*H
#define LB (L*B)        // 16384

// ---------------- scratch (static device globals; no allocation) ----------------
__device__ float g_tp[LB*H];            // tanh(Wp  v)     [i,b,h]
__device__ float g_u [LB*H];            // V * tp          [i,b,h]
__device__ float g_tq[LB*H];            // tanh(Wp_ v)     [l,b,h]
__device__ float g_w [LB*H];            // V * tq          [l,b,h]
__device__ float g_S [LB*L];            // scores/softmax  [i,b,l]
__device__ float g_c [LB*D];            // context         [i,b,d]
__device__ float g_gi[LB*G];            // W_ih c + b_ih   [i,b,3H]

// ---------------- helpers ----------------
__device__ __forceinline__ float frcp_approx(float x) {
    float r;
    asm("rcp.approx.f32 %0, %1;" : "=f"(r) : "f"(x));
    return r;
}

// tanh via ex2/rcp: tanh(x) = 1 - 2/(e^{2x}+1).  rel err ~1e-6.
__device__ __forceinline__ float fast_tanh(float x) {
    float t;
    asm("ex2.approx.f32 %0, %1;" : "=f"(t) : "f"(x * 2.8853900817779268f));
    float r = frcp_approx(t + 1.0f);
    return fmaf(-2.0f, r, 1.0f);
}

__device__ __forceinline__ uint32_t smem_u32(const void* p) {
    uint32_t a;
    asm("{ .reg .u64 t; cvta.to.shared.u64 t, %1; cvt.u32.u64 %0, t; }" : "=r"(a) : "l"(p));
    return a;
}

__device__ __forceinline__ void st_shared_cluster_f32(uint32_t laddr, uint32_t rank, float v) {
    asm volatile(
        "{ .reg .b32 ra; mapa.shared::cluster.u32 ra, %0, %1; st.shared::cluster.f32 [ra], %2; }"
        :: "r"(laddr), "r"(rank), "f"(v) : "memory");
}

__device__ __forceinline__ void cluster_sync_all() {
    asm volatile("barrier.cluster.arrive.aligned;" ::: "memory");
    asm volatile("barrier.cluster.wait.aligned;" ::: "memory");
}

__device__ __forceinline__ void mbar_init(uint32_t a, uint32_t cnt) {
    asm volatile("mbarrier.init.shared.b64 [%0], %1;" :: "r"(a), "r"(cnt) : "memory");
}
__device__ __forceinline__ void mbar_arrive_remote(uint32_t a, uint32_t rank) {
    asm volatile(
        "{ .reg .b32 ra; mapa.shared::cluster.u32 ra, %0, %1; "
        "mbarrier.arrive.release.cluster.shared::cluster.b64 _, [ra]; }"
        :: "r"(a), "r"(rank) : "memory");
}
__device__ __forceinline__ void mbar_wait_parity(uint32_t a, uint32_t phase) {
    asm volatile(
        "{\n\t.reg .pred P;\n\t"
        "WL%=:\n\t"
        "mbarrier.try_wait.parity.acquire.cluster.shared::cta.b64 P, [%0], %1, 0x989680;\n\t"
        "@P bra WD%=;\n\t"
        "bra WL%=;\n\t"
        "WD%=:\n\t}"
        :: "r"(a), "r"(phase) : "memory");
}

// packed f32x2
#define FMA2(d, a, b) asm("fma.rn.f32x2 %0, %1, %2, %0;" : "+l"(d) : "l"(a), "l"(b))
#define PK(v, lo, hi) asm("mov.b64 %0, {%1, %2};" : "=l"(v) : "f"(lo), "f"(hi))
#define UNPK(lo, hi, v) asm("mov.b64 {%0, %1}, %2;" : "=f"(lo), "=f"(hi) : "l"(v))

// ---------------- 1) projection GEMM (f32x2) + tanh epilogue ----------------
// T[n,h] = tanh( sum_k X[n,k] W[h,k] ),  Uo[n,h] = Vv[n&31, h] * T[n,h]
// 128x128 tile, 8x8 microtile, k-chunk 8.
__global__ __launch_bounds__(256) void proj_kernel(
    const float* __restrict__ X, const float* __restrict__ W,
    const float* __restrict__ Vv, float* __restrict__ T, float* __restrict__ Uo)
{
    __shared__ float As[8][132];
    __shared__ float Bs[8][132];
    int n0 = blockIdx.y * 128, h0 = blockIdx.x * 128;
    int tid = threadIdx.x;
    int r = tid >> 1, q4 = (tid & 1) * 4;
    int tx = tid & 15, ty = tid >> 4;

    const float* pa = X + (n0 + r) * 256 + q4;
    const float* pb = W + (h0 + r) * 256 + q4;
    float4 av = *(const float4*)pa;
    float4 bv = *(const float4*)pb;

    unsigned long long acc[8][4] = {};

    #pragma unroll 1
    for (int k0 = 0; k0 < 256; k0 += 8) {
        As[q4+0][r] = av.x; As[q4+1][r] = av.y; As[q4+2][r] = av.z; As[q4+3][r] = av.w;
        Bs[q4+0][r] = bv.x; Bs[q4+1][r] = bv.y; Bs[q4+2][r] = bv.z; Bs[q4+3][r] = bv.w;
        __syncthreads();
        if (k0 + 8 < 256) {
            av = *(const float4*)(pa + k0 + 8);
            bv = *(const float4*)(pb + k0 + 8);
        }
        #pragma unroll
        for (int kk = 0; kk < 8; ++kk) {
            float4 a0 = *(const float4*)&As[kk][ty * 4];
            float4 a1 = *(const float4*)&As[kk][64 + ty * 4];
            ulonglong2 b0 = *(const ulonglong2*)&Bs[kk][tx * 4];
            ulonglong2 b1 = *(const ulonglong2*)&Bs[kk][64 + tx * 4];
            float aa[8] = {a0.x, a0.y, a0.z, a0.w, a1.x, a1.y, a1.z, a1.w};
            #pragma unroll
            for (int i = 0; i < 8; ++i) {
                unsigned long long ap; PK(ap, aa[i], aa[i]);
                FMA2(acc[i][0], ap, b0.x);
                FMA2(acc[i][1], ap, b0.y);
                FMA2(acc[i][2], ap, b1.x);
                FMA2(acc[i][3], ap, b1.y);
            }
        }
        __syncthreads();
    }
    #pragma unroll
    for (int i = 0; i < 8; ++i) {
        int n = n0 + (i < 4 ? ty * 4 + i : 64 + ty * 4 + (i - 4));
        int bb = n & 31;
        #pragma unroll
        for (int j = 0; j < 4; ++j) {
            int h = h0 + (j < 2 ? tx * 4 + 2 * j : 64 + tx * 4 + 2 * (j - 2));
            float lo, hi; UNPK(lo, hi, acc[i][j]);
            float t0 = fast_tanh(lo), t1 = fast_tanh(hi);
            *(float2*)&T[n * 256 + h] = make_float2(t0, t1);
            float v0 = Vv[bb * 256 + h], v1 = Vv[bb * 256 + h + 1];
            *(float2*)&Uo[n * 256 + h] = make_float2(v0 * t0, v1 * t1);
        }
    }
}

// ---------------- 2) scores: S[i,b,l] = sum_h (u_i + w_l) / (1 + tp_i*tq_l) ----------------
__global__ __launch_bounds__(256) void scores_kernel()
{
    __shared__ float TPs[64][33], Us[64][33], TQs[64][33], WWs[64][33];
    int b = blockIdx.z;
    int l0 = blockIdx.x * 64, i0 = blockIdx.y * 64;
    int t = threadIdx.x;
    int ti = t >> 4, tl = t & 15;
    float acc[4][4] = {};

    for (int h0 = 0; h0 < 256; h0 += 32) {
        #pragma unroll
        for (int it = 0; it < 8; ++it) {
            int idx = t + it * 256;
            int r = idx >> 5, kk = idx & 31;
            int io = ((i0 + r) * 32 + b) * 256 + h0 + kk;
            int lo = ((l0 + r) * 32 + b) * 256 + h0 + kk;
            TPs[r][kk] = g_tp[io];
            Us [r][kk] = g_u [io];
            TQs[r][kk] = g_tq[lo];
            WWs[r][kk] = g_w [lo];
        }
        __syncthreads();
        #pragma unroll
        for (int kk = 0; kk < 32; ++kk) {
            float tp[4], uu[4], tq[4], ww[4];
            #pragma unroll
            for (int i = 0; i < 4; ++i) { tp[i] = TPs[ti * 4 + i][kk]; uu[i] = Us[ti * 4 + i][kk]; }
            #pragma unroll
            for (int j = 0; j < 4; ++j) { tq[j] = TQs[tl + 16 * j][kk]; ww[j] = WWs[tl + 16 * j][kk]; }
            #pragma unroll
            for (int i = 0; i < 4; ++i)
                #pragma unroll
                for (int j = 0; j < 4; ++j) {
                    float den = fmaf(tp[i], tq[j], 1.0f);
                    float rr  = frcp_approx(den);
                    acc[i][j] = fmaf(uu[i] + ww[j], rr, acc[i][j]);
                }
        }
        __syncthreads();
    }
    #pragma unroll
    for (int i = 0; i < 4; ++i)
        #pragma unroll
        for (int j = 0; j < 4; ++j)
            g_S[((i0 + ti * 4 + i) * 32 + b) * 512 + l0 + tl + 16 * j] = acc[i][j];
}

// ---------------- 3) softmax over l, in place on g_S ----------------
__global__ __launch_bounds__(128) void softmax_kernel()
{
    int row = blockIdx.x;
    float* p = g_S + (size_t)row * 512;
    int t = threadIdx.x;
    float4 x = reinterpret_cast<float4*>(p)[t];
    float m = fmaxf(fmaxf(x.x, x.y), fmaxf(x.z, x.w));
    #pragma unroll
    for (int o = 16; o; o >>= 1) m = fmaxf(m, __shfl_xor_sync(0xffffffffu, m, o));
    __shared__ float redm[4];
    if ((t & 31) == 0) redm[t >> 5] = m;
    __syncthreads();
    m = fmaxf(fmaxf(redm[0], redm[1]), fmaxf(redm[2], redm[3]));
    float e0 = expf(x.x - m), e1 = expf(x.y - m), e2 = expf(x.z - m), e3 = expf(x.w - m);
    float s = e0 + e1 + e2 + e3;
    #pragma unroll
    for (int o = 16; o; o >>= 1) s += __shfl_xor_sync(0xffffffffu, s, o);
    __shared__ float reds[4];
    if ((t & 31) == 0) reds[t >> 5] = s;
    __syncthreads();
    s = reds[0] + reds[1] + reds[2] + reds[3];
    float inv = 1.0f / s;
    reinterpret_cast<float4*>(p)[t] = make_float4(e0 * inv, e1 * inv, e2 * inv, e3 * inv);
}

// ---------------- 4) context (f32x2): c[i,b,d] = sum_l A[i,b,l]*v[l,b,d] ----------------
// Per batch: M=512(i), N=256(d), K=512(l). A transposed-load, B direct-load.
__global__ __launch_bounds__(256) void context_kernel(const float* __restrict__ v)
{
    __shared__ float As[8][132];
    __shared__ float Bs[8][132];
    int b  = blockIdx.z;
    int i0 = blockIdx.y * 128, d0 = blockIdx.x * 128;
    int tid = threadIdx.x;
    int r = tid >> 1, q4 = (tid & 1) * 4;       // A loader mapping
    int lrow = tid >> 5, dc = (tid & 31) * 4;   // B loader mapping
    int tx = tid & 15, ty = tid >> 4;

    const float* pa = g_S + (size_t)((i0 + r) * 32 + b) * 512 + q4;
    const float* pb = v + (size_t)(lrow * 32 + b) * 256 + d0 + dc;
    float4 av = *(const float4*)pa;
    float4 bv = *(const float4*)pb;

    unsigned long long acc[8][4] = {};

    #pragma unroll 1
    for (int k0 = 0; k0 < 512; k0 += 8) {
        As[q4+0][r] = av.x; As[q4+1][r] = av.y; As[q4+2][r] = av.z; As[q4+3][r] = av.w;
        *(float4*)&Bs[lrow][dc] = bv;
        __syncthreads();
        if (k0 + 8 < 512) {
            av = *(const float4*)(pa + k0 + 8);
            bv = *(const float4*)(pb + (size_t)(k0 + 8) * 8192);
        }
        #pragma unroll
        for (int kk = 0; kk < 8; ++kk) {
            float4 a0 = *(const float4*)&As[kk][ty * 4];
            float4 a1 = *(const float4*)&As[kk][64 + ty * 4];
            ulonglong2 b0 = *(const ulonglong2*)&Bs[kk][tx * 4];
            ulonglong2 b1 = *(const ulonglong2*)&Bs[kk][64 + tx * 4];
            float aa[8] = {a0.x, a0.y, a0.z, a0.w, a1.x, a1.y, a1.z, a1.w};
            #pragma unroll
            for (int i = 0; i < 8; ++i) {
                unsigned long long ap; PK(ap, aa[i], aa[i]);
                FMA2(acc[i][0], ap, b0.x);
                FMA2(acc[i][1], ap, b0.y);
                FMA2(acc[i][2], ap, b1.x);
                FMA2(acc[i][3], ap, b1.y);
            }
        }
        __syncthreads();
    }
    #pragma unroll
    for (int i = 0; i < 8; ++i) {
        int row = i0 + (i < 4 ? ty * 4 + i : 64 + ty * 4 + (i - 4));
        #pragma unroll
        for (int j = 0; j < 4; ++j) {
            int d = d0 + (j < 2 ? tx * 4 + 2 * j : 64 + tx * 4 + 2 * (j - 2));
            float lo, hi; UNPK(lo, hi, acc[i][j]);
            *(float2*)&g_c[(size_t)(row * 32 + b) * 256 + d] = make_float2(lo, hi);
        }
    }
}

// ---------------- 5) gi (f32x2) = c @ W_ih^T + b_ih ----------------
__global__ __launch_bounds__(256) void gi_kernel(const float* __restrict__ W_ih,
                                                 const float* __restrict__ b_ih)
{
    __shared__ float As[8][132];
    __shared__ float Bs[8][132];
    int n0 = blockIdx.y * 128, j0 = blockIdx.x * 128;
    int tid = threadIdx.x;
    int r = tid >> 1, q4 = (tid & 1) * 4;
    int tx = tid & 15, ty = tid >> 4;

    const float* pa = g_c + (size_t)(n0 + r) * 256 + q4;
    const float* pb = W_ih + (size_t)(j0 + r) * 256 + q4;
    float4 av = *(const float4*)pa;
    float4 bv = *(const float4*)pb;

    unsigned long long acc[8][4] = {};

    #pragma unroll 1
    for (int k0 = 0; k0 < 256; k0 += 8) {
        As[q4+0][r] = av.x; As[q4+1][r] = av.y; As[q4+2][r] = av.z; As[q4+3][r] = av.w;
        Bs[q4+0][r] = bv.x; Bs[q4+1][r] = bv.y; Bs[q4+2][r] = bv.z; Bs[q4+3][r] = bv.w;
        __syncthreads();
        if (k0 + 8 < 256) {
            av = *(const float4*)(pa + k0 + 8);
            bv = *(const float4*)(pb + k0 + 8);
        }
        #pragma unroll
        for (int kk = 0; kk < 8; ++kk) {
            float4 a0 = *(const float4*)&As[kk][ty * 4];
            float4 a1 = *(const float4*)&As[kk][64 + ty * 4];
            ulonglong2 b0 = *(const ulonglong2*)&Bs[kk][tx * 4];
            ulonglong2 b1 = *(const ulonglong2*)&Bs[kk][64 + tx * 4];
            float aa[8] = {a0.x, a0.y, a0.z, a0.w, a1.x, a1.y, a1.z, a1.w};
            #pragma unroll
            for (int i = 0; i < 8; ++i) {
                unsigned long long ap; PK(ap, aa[i], aa[i]);
                FMA2(acc[i][0], ap, b0.x);
                FMA2(acc[i][1], ap, b0.y);
                FMA2(acc[i][2], ap, b1.x);
                FMA2(acc[i][3], ap, b1.y);
            }
        }
        __syncthreads();
    }
    #pragma unroll
    for (int i = 0; i < 8; ++i) {
        int n = n0 + (i < 4 ? ty * 4 + i : 64 + ty * 4 + (i - 4));
        #pragma unroll
        for (int j = 0; j < 4; ++j) {
            int jj = j0 + (j < 2 ? tx * 4 + 2 * j : 64 + tx * 4 + 2 * (j - 2));
            float lo, hi; UNPK(lo, hi, acc[i][j]);
            float2 bias = *(const float2*)&b_ih[jj];
            *(float2*)&g_gi[(size_t)n * 768 + jj] = make_float2(lo + bias.x, hi + bias.y);
        }
    }
}

// ---------------- 6) GRU recurrence: cluster of 8 CTAs per batch ----------------
// Rank k owns 96 rows (3 gates x 32 h-slice) of W_hh, held in REGISTERS:
// 192 threads, thread pair (2r, 2r+1) splits row r's 256 weights in half.
// Per step: packed-FMA register GEMV + pair-shfl, gates on 32 threads,
// DSMEM broadcast of the 32 new h values, mbarrier (count 256) sync.
__global__ void __cluster_dims__(8, 1, 1) __launch_bounds__(192, 2)
gru_kernel(const float* __restrict__ h0in, const float* __restrict__ W_hh,
           const float* __restrict__ b_hh, float* __restrict__ hs)
{
    __shared__ __align__(16) float hbuf[2][256];
    __shared__ float gh_s[96];
    __shared__ float bhh_s[96];
    __shared__ __align__(8) unsigned long long mbar;

    int tid  = threadIdx.x;               // 192 threads
    int b    = blockIdx.x >> 3;
    int rank = blockIdx.x & 7;
    int row  = tid >> 1, half = tid & 1;  // row 0..95
    int grow = (row >> 5) * 256 + rank * 32 + (row & 31);

    // 128 weights -> 64 registers as packed f32 pairs
    ulonglong2 wv[32];
    const ulonglong2* wsrc = (const ulonglong2*)(W_hh + (size_t)grow * 256 + half * 128);
    #pragma unroll
    for (int q = 0; q < 32; ++q) wv[q] = wsrc[q];

    if (tid < 96) bhh_s[tid] = b_hh[(tid >> 5) * 256 + rank * 32 + (tid & 31)];
    if (tid < 64) ((float4*)hbuf[0])[tid] = ((const float4*)(h0in + b * 256))[tid];
    uint32_t mb = smem_u32(&mbar);
    if (tid == 0) mbar_init(mb, 256);
    __syncthreads();
    cluster_sync_all();   // mbarriers + h0 visible cluster-wide before traffic

    int p = 0;
    for (int i = 0; i < 512; ++i) {
        // prefetch gi (independent of h)
        float ir = 0.f, iz = 0.f, inn = 0.f;
        if (tid < 32) {
            const float* gg = g_gi + ((size_t)i * 32 + b) * 768;
            int jg = rank * 32 + tid;
            ir = gg[jg]; iz = gg[256 + jg]; inn = gg[512 + jg];
        }
        const ulonglong2* h2 = (const ulonglong2*)(hbuf[p] + half * 128);
        unsigned long long acc2 = 0;
        #pragma unroll
        for (int q = 0; q < 32; ++q) {
            ulonglong2 hh = h2[q];
            FMA2(acc2, wv[q].x, hh.x);
            FMA2(acc2, wv[q].y, hh.y);
        }
        float alo, ahi; UNPK(alo, ahi, acc2);
        float acc = alo + ahi;
        acc += __shfl_xor_sync(0xffffffffu, acc, 1);
        if (half == 0) gh_s[row] = acc + bhh_s[row];
        __syncthreads();
        if (tid < 32) {
            int jg = rank * 32 + tid;
            float r = 1.0f / (1.0f + expf(-(ir + gh_s[tid])));
            float z = 1.0f / (1.0f + expf(-(iz + gh_s[tid + 32])));
            float n = tanhf(inn + r * gh_s[tid + 64]);
            float hold = hbuf[p][jg];
            float hnew = fmaf(z, hold - n, n);
            hs[((size_t)i * 32 + b) * 256 + jg] = hnew;
            if (i < 511) {
                uint32_t laddr = smem_u32(&hbuf[1 - p][jg]);
                #pragma unroll
                for (uint32_t rr = 0; rr < 8; ++rr) st_shared_cluster_f32(laddr, rr, hnew);
                #pragma unroll
                for (uint32_t rr = 0; rr < 8; ++rr) mbar_arrive_remote(mb, rr);
            }
        }
        if (i < 511) mbar_wait_parity(mb, i & 1);
        p ^= 1;
    }
}

// ---------------- launch ----------------
extern "C" void kernel_launch(void* const* d_in, const int* in_sizes, int n_in,
                              void* d_out, int out_size)
{
    const float* v    = (const float*)d_in[0];
    const float* h0   = (const float*)d_in[1];
    const float* Vv   = (const float*)d_in[2];
    const float* Wp   = (const float*)d_in[3];
    const float* Wp_  = (const float*)d_in[4];
    const float* W_ih = (const float*)d_in[5];
    const float* W_hh = (const float*)d_in[6];
    const float* b_ih = (const float*)d_in[7];
    const float* b_hh = (const float*)d_in[8];
    float* hs = (float*)d_out;
    (void)in_sizes; (void)n_in; (void)out_size;

    float *d_tp = 0, *d_u = 0, *d_tq = 0, *d_w = 0;
    cudaGetSymbolAddress((void**)&d_tp, g_tp);
    cudaGetSymbolAddress((void**)&d_u,  g_u);
    cudaGetSymbolAddress((void**)&d_tq, g_tq);
    cudaGetSymbolAddress((void**)&d_w,  g_w);

    proj_kernel<<<dim3(2, 128), 256>>>(v, Wp,  Vv, d_tp, d_u);
    proj_kernel<<<dim3(2, 128), 256>>>(v, Wp_, Vv, d_tq, d_w);
    scores_kernel<<<dim3(8, 8, 32), 256>>>();
    softmax_kernel<<<LB, 128>>>();
    context_kernel<<<dim3(2, 4, 32), 256>>>(v);
    gi_kernel<<<dim3(6, 128), 256>>>(W_ih, b_ih);
    gru_kernel<<<B * 8, 192>>>(h0, W_hh, b_hh, hs);
}